// round 16
// baseline (speedup 1.0000x reference)
#include <cuda_runtime.h>
#include <cuda_bf16.h>
#include <cstdint>
#include <cstddef>

// Problem shape (fixed by reference): B=16, T=1024, D=256
#define BB 16
#define TT 1024
#define DD 256

#define TILE 128      // (t,s) tile per CTA
#define KC   32       // K chunk staged through smem (8 chunks)
#define STRIDE 40     // bf16 units per smem row (32+8 pad): conflict-free, 16B-aligned rows

#define C_YX 61.72839506172839f   // 1/(2*0.09^2)
#define C_HW 5.555555555555555f   // 1/(2*0.3^2)

__device__ float g_num[BB];
__device__ float g_den[BB];
__device__ __nv_bfloat16 g_zb[BB * TT * DD];   // bf16 copy of z (8.4 MB scratch)

__device__ __forceinline__ void cp16(void* dst, const void* src) {
    uint32_t d = (uint32_t)__cvta_generic_to_shared(dst);
    asm volatile("cp.async.cg.shared.global [%0], [%1], 16;\n" :: "r"(d), "l"(src));
}
__device__ __forceinline__ void prefetch_l2(const void* p) {
    asm volatile("prefetch.global.L2 [%0];" :: "l"(p));
}
__device__ __forceinline__ void mma_bf16(float c[4], const uint32_t a[4], const uint32_t b[2]) {
    asm volatile(
        "mma.sync.aligned.m16n8k16.row.col.f32.bf16.bf16.f32 "
        "{%0,%1,%2,%3}, {%4,%5,%6,%7}, {%8,%9}, {%0,%1,%2,%3};"
        : "+f"(c[0]), "+f"(c[1]), "+f"(c[2]), "+f"(c[3])
        : "r"(a[0]), "r"(a[1]), "r"(a[2]), "r"(a[3]), "r"(b[0]), "r"(b[1]));
}

// ---------------------------------------------------------------------------
// Prep: z (fp32, read-once -> ldcs) -> g_zb (bf16); zero accumulators.
// 512 blocks x 256 threads, 8 float4/thread front-batched.
// ---------------------------------------------------------------------------
__global__ void prep_kernel(const float4* __restrict__ z4) {
    if (blockIdx.x == 0 && threadIdx.x < BB) {
        g_num[threadIdx.x] = 0.0f;
        g_den[threadIdx.x] = 0.0f;
    }
    int base = blockIdx.x * 2048 + threadIdx.x;
    float4 v[8];
#pragma unroll
    for (int i = 0; i < 8; i++) v[i] = __ldcs(&z4[base + i * 256]);
#pragma unroll
    for (int i = 0; i < 8; i++) {
        __nv_bfloat162 lo = __floats2bfloat162_rn(v[i].x, v[i].y);
        __nv_bfloat162 hi = __floats2bfloat162_rn(v[i].z, v[i].w);
        uint2 pk;
        pk.x = *(uint32_t*)&lo;
        pk.y = *(uint32_t*)&hi;
        *(uint2*)(g_zb + (size_t)(base + i * 256) * 4) = pk;
    }
}

// ---------------------------------------------------------------------------
// Fused (champion + full upfront L2 prefetch):
//  Step 0: every thread issues 8 prefetch.global.L2 covering this CTA's full
//          256KB dT tile (2048 x 128B lines) BEFORE the GEMM -> maximum lead
//          time; DRAM streams the tile in while tensor cores run.
//  Phase 1: 128x128 Gram tile via bf16 mma.sync, cp.async double-buffered;
//           one re-touch prefetch per thread per K-chunk (L2 hit if resident).
//  Phase 2: epilogue streams the dT tile (L2-hot), w = exp(-e),
//           accumulates Sum w and Sum w*(2-2G)   (z L2-normalized -> z2=1).
// grid = (8,8,16), block = 256 (8 warps; 2x4 warp grid, 64x32 per warp).
// ---------------------------------------------------------------------------
__global__ __launch_bounds__(256, 2)
void fused_kernel(const float4* __restrict__ dT4) {
    __shared__ __nv_bfloat16 smA[2][TILE * STRIDE];
    __shared__ __nv_bfloat16 smB[2][TILE * STRIDE];
    __shared__ float red0[8], red1[8];

    const int b  = blockIdx.z;
    const int t0 = blockIdx.y * TILE;
    const int s0 = blockIdx.x * TILE;

    const __nv_bfloat16* zbA = g_zb + (size_t)b * TT * DD + (size_t)t0 * DD;
    const __nv_bfloat16* zbB = g_zb + (size_t)b * TT * DD + (size_t)s0 * DD;

    const int tid  = threadIdx.x;
    const int warp = tid >> 5;
    const int lane = tid & 31;
    const int wm   = warp & 1;   // row half (64 rows)
    const int wn   = warp >> 1;  // col quarter (32 cols)
    const int g    = lane >> 2;
    const int tg   = lane & 3;

    const size_t dbase = (size_t)b * TT * TT + (size_t)t0 * TT + s0;
    const char* dT_tile = (const char*)(dT4 + dbase);

    // ---- Step 0: prefetch the ENTIRE dT tile upfront (8 lines/thread) ------
#pragma unroll
    for (int i = 0; i < 8; i++) {
        const int L = i * 256 + tid;      // 0..2047 ; row = L>>4, 128B chunk = L&15
        prefetch_l2(dT_tile + (size_t)(L >> 4) * (TT * 16) + (size_t)(L & 15) * 128);
    }

    // staging coords (R7-proven): sr = row, sc = 16B unit within 32-col row
    const int sr0 = tid >> 2, sc0 = tid & 3;
    const int sr1 = (tid + 256) >> 2, sc1 = (tid + 256) & 3;

    float acc[16][4];
#pragma unroll
    for (int i = 0; i < 16; i++)
#pragma unroll
        for (int j = 0; j < 4; j++) acc[i][j] = 0.0f;

    // ---- prologue: stage chunk 0 into buffer 0 ----
    cp16(&smA[0][sr0 * STRIDE + sc0 * 8], zbA + (size_t)sr0 * DD + sc0 * 8);
    cp16(&smB[0][sr0 * STRIDE + sc0 * 8], zbB + (size_t)sr0 * DD + sc0 * 8);
    cp16(&smA[0][sr1 * STRIDE + sc1 * 8], zbA + (size_t)sr1 * DD + sc1 * 8);
    cp16(&smB[0][sr1 * STRIDE + sc1 * 8], zbB + (size_t)sr1 * DD + sc1 * 8);
    asm volatile("cp.async.commit_group;\n" ::);

#pragma unroll
    for (int kci = 0; kci < DD / KC; kci++) {
        // re-touch prefetch (cheap L2 hit if still resident, re-fetch if evicted)
        {
            const int L = kci * 256 + tid;
            prefetch_l2(dT_tile + (size_t)(L >> 4) * (TT * 16) + (size_t)(L & 15) * 128);
        }

        if (kci < DD / KC - 1) {
            const int kn = (kci + 1) * KC;
            const int nb = (kci + 1) & 1;
            cp16(&smA[nb][sr0 * STRIDE + sc0 * 8], zbA + (size_t)sr0 * DD + kn + sc0 * 8);
            cp16(&smB[nb][sr0 * STRIDE + sc0 * 8], zbB + (size_t)sr0 * DD + kn + sc0 * 8);
            cp16(&smA[nb][sr1 * STRIDE + sc1 * 8], zbA + (size_t)sr1 * DD + kn + sc1 * 8);
            cp16(&smB[nb][sr1 * STRIDE + sc1 * 8], zbB + (size_t)sr1 * DD + kn + sc1 * 8);
            asm volatile("cp.async.commit_group;\n" ::);
            asm volatile("cp.async.wait_group 1;\n" ::);
        } else {
            asm volatile("cp.async.wait_group 0;\n" ::);
        }
        __syncthreads();

        const __nv_bfloat16* A = smA[kci & 1];
        const __nv_bfloat16* B = smB[kci & 1];
#pragma unroll
        for (int k0 = 0; k0 < KC; k0 += 16) {
            uint32_t af[4][4], bf[4][2];
            const int ak = k0 + 2 * tg;
#pragma unroll
            for (int mi = 0; mi < 4; mi++) {
                const __nv_bfloat16* p = &A[(wm * 64 + mi * 16 + g) * STRIDE + ak];
                af[mi][0] = *(const uint32_t*)(p);
                af[mi][1] = *(const uint32_t*)(p + 8 * STRIDE);
                af[mi][2] = *(const uint32_t*)(p + 8);
                af[mi][3] = *(const uint32_t*)(p + 8 * STRIDE + 8);
            }
#pragma unroll
            for (int ni = 0; ni < 4; ni++) {
                const __nv_bfloat16* p = &B[(wn * 32 + ni * 8 + g) * STRIDE + ak];
                bf[ni][0] = *(const uint32_t*)(p);
                bf[ni][1] = *(const uint32_t*)(p + 8);
            }
#pragma unroll
            for (int mi = 0; mi < 4; mi++)
#pragma unroll
                for (int ni = 0; ni < 4; ni++)
                    mma_bf16(acc[mi * 4 + ni], af[mi], bf[ni]);
        }
        __syncthreads();  // all warps done reading this buffer before restage
    }

    // ---- Epilogue: stream dT tile (L2-hot), accumulate -----------------------
    float sum_w = 0.0f, sum_num = 0.0f;
#pragma unroll
    for (int mi = 0; mi < 4; mi++) {
#pragma unroll
        for (int ni = 0; ni < 4; ni++) {
#pragma unroll
            for (int j = 0; j < 4; j++) {
                int tt = wm * 64 + mi * 16 + g + ((j >> 1) ? 8 : 0);
                int ss = wn * 32 + ni * 8 + 2 * tg + (j & 1);
                float4 d4 = __ldg(&dT4[dbase + (size_t)tt * TT + ss]);
                float e = (d4.x * d4.x + d4.y * d4.y) * C_YX
                        + (d4.z * d4.z + d4.w * d4.w) * C_HW;
                float w = __expf(-e);
                float G = acc[mi * 4 + ni][j];
                sum_w   += w;
                sum_num += w * (2.0f - 2.0f * G);   // z2_t = z2_s = 1
            }
        }
    }

#pragma unroll
    for (int o = 16; o > 0; o >>= 1) {
        sum_w   += __shfl_down_sync(0xFFFFFFFFu, sum_w,   o);
        sum_num += __shfl_down_sync(0xFFFFFFFFu, sum_num, o);
    }
    if (lane == 0) { red0[warp] = sum_w; red1[warp] = sum_num; }
    __syncthreads();
    if (tid == 0) {
        float W = 0.0f, NUM = 0.0f;
#pragma unroll
        for (int i = 0; i < 8; i++) { W += red0[i]; NUM += red1[i]; }
        atomicAdd(&g_den[b], W);
        atomicAdd(&g_num[b], NUM);
    }
}

// ---------------------------------------------------------------------------
// Finalize: mean over batches of num / max(den, 1e-6)
// ---------------------------------------------------------------------------
__global__ void final_kernel(float* __restrict__ out) {
    int lane = threadIdx.x;
    float r = 0.0f;
    if (lane < BB) r = g_num[lane] / fmaxf(g_den[lane], 1e-6f);
#pragma unroll
    for (int o = 16; o > 0; o >>= 1) r += __shfl_down_sync(0xFFFFFFFFu, r, o);
    if (lane == 0) out[0] = r * (1.0f / BB);
}

extern "C" void kernel_launch(void* const* d_in, const int* in_sizes, int n_in,
                              void* d_out, int out_size) {
    const float* z  = (const float*)d_in[0];
    const float* dT = (const float*)d_in[1];
    // Defensive: z has B*T*D = 4.19M elems, gt_dT has B*T*T*4 = 67.1M.
    if (n_in >= 2 && in_sizes[0] > in_sizes[1]) {
        const float* tmp = z; z = dT; dT = tmp;
    }
    (void)out_size;

    prep_kernel<<<512, 256>>>((const float4*)z);

    dim3 grid(TT / TILE, TT / TILE, BB);
    fused_kernel<<<grid, 256>>>((const float4*)dT);

    final_kernel<<<1, 32>>>((float*)d_out);
}

// round 17
// speedup vs baseline: 1.1361x; 1.1361x over previous
#include <cuda_runtime.h>
#include <cuda_bf16.h>
#include <cstdint>
#include <cstddef>

// Problem shape (fixed by reference): B=16, T=1024, D=256
#define BB 16
#define TT 1024
#define DD 256

#define TILE 128      // (t,s) tile per CTA
#define KC   32       // K chunk staged through smem (8 chunks)
#define STRIDE 40     // bf16 units per smem row (32+8 pad): conflict-free, 16B-aligned rows

#define C_YX 61.72839506172839f   // 1/(2*0.09^2)
#define C_HW 5.555555555555555f   // 1/(2*0.3^2)

__device__ float g_num[BB];
__device__ float g_den[BB];
__device__ __nv_bfloat16 g_zb[BB * TT * DD];   // bf16 copy of z (8.4 MB scratch)

__device__ __forceinline__ void cp16(void* dst, const void* src) {
    uint32_t d = (uint32_t)__cvta_generic_to_shared(dst);
    asm volatile("cp.async.cg.shared.global [%0], [%1], 16;\n" :: "r"(d), "l"(src));
}
__device__ __forceinline__ void prefetch_l2(const void* p) {
    asm volatile("prefetch.global.L2 [%0];" :: "l"(p));
}
__device__ __forceinline__ void mma_bf16(float c[4], const uint32_t a[4], const uint32_t b[2]) {
    asm volatile(
        "mma.sync.aligned.m16n8k16.row.col.f32.bf16.bf16.f32 "
        "{%0,%1,%2,%3}, {%4,%5,%6,%7}, {%8,%9}, {%0,%1,%2,%3};"
        : "+f"(c[0]), "+f"(c[1]), "+f"(c[2]), "+f"(c[3])
        : "r"(a[0]), "r"(a[1]), "r"(a[2]), "r"(a[3]), "r"(b[0]), "r"(b[1]));
}

// ---------------------------------------------------------------------------
// Prep: z (fp32) -> g_zb (bf16); zero accumulators. 1024x256, 4 f4/thread.
// ---------------------------------------------------------------------------
__global__ void prep_kernel(const float4* __restrict__ z4) {
    if (blockIdx.x == 0 && threadIdx.x < BB) {
        g_num[threadIdx.x] = 0.0f;
        g_den[threadIdx.x] = 0.0f;
    }
    int base = blockIdx.x * 1024 + threadIdx.x;
#pragma unroll
    for (int i = 0; i < 4; i++) {
        int idx = base + i * 256;
        float4 v = z4[idx];
        __nv_bfloat162 lo = __floats2bfloat162_rn(v.x, v.y);
        __nv_bfloat162 hi = __floats2bfloat162_rn(v.z, v.w);
        uint2 pk;
        pk.x = *(uint32_t*)&lo;
        pk.y = *(uint32_t*)&hi;
        *(uint2*)(g_zb + (size_t)idx * 4) = pk;
    }
}

// ---------------------------------------------------------------------------
// Fused (R15 champion + accelerated-but-paced L2 prefetch):
//  Phase 1: 128x128 Gram tile via bf16 mma.sync, cp.async double-buffered;
//           iterations 0..3 each issue 2 prefetch.global.L2 per thread on
//           this CTA's dT tile (full 2048 x 128B lines requested by mid-GEMM,
//           so even tail lines get ~half a GEMM window of lead time; request
//           rate stays paced -> no queue flooding like a front-loaded burst).
//  Phase 2: epilogue streams the dT tile (L2-hot), w = exp(-e),
//           accumulates Sum w and Sum w*(2-2G)   (z L2-normalized -> z2=1).
// grid = (8,8,16), block = 256 (8 warps; 2x4 warp grid, 64x32 per warp).
// ---------------------------------------------------------------------------
__global__ __launch_bounds__(256, 2)
void fused_kernel(const float4* __restrict__ dT4) {
    __shared__ __nv_bfloat16 smA[2][TILE * STRIDE];
    __shared__ __nv_bfloat16 smB[2][TILE * STRIDE];
    __shared__ float red0[8], red1[8];

    const int b  = blockIdx.z;
    const int t0 = blockIdx.y * TILE;
    const int s0 = blockIdx.x * TILE;

    const __nv_bfloat16* zbA = g_zb + (size_t)b * TT * DD + (size_t)t0 * DD;
    const __nv_bfloat16* zbB = g_zb + (size_t)b * TT * DD + (size_t)s0 * DD;

    const int tid  = threadIdx.x;
    const int warp = tid >> 5;
    const int lane = tid & 31;
    const int wm   = warp & 1;   // row half (64 rows)
    const int wn   = warp >> 1;  // col quarter (32 cols)
    const int g    = lane >> 2;
    const int tg   = lane & 3;

    const size_t dbase = (size_t)b * TT * TT + (size_t)t0 * TT + s0;
    const char* dT_tile = (const char*)(dT4 + dbase);

    // staging coords (R7-proven): sr = row, sc = 16B unit within 32-col row
    const int sr0 = tid >> 2, sc0 = tid & 3;
    const int sr1 = (tid + 256) >> 2, sc1 = (tid + 256) & 3;

    float acc[16][4];
#pragma unroll
    for (int i = 0; i < 16; i++)
#pragma unroll
        for (int j = 0; j < 4; j++) acc[i][j] = 0.0f;

    // ---- prologue: stage chunk 0 into buffer 0 ----
    cp16(&smA[0][sr0 * STRIDE + sc0 * 8], zbA + (size_t)sr0 * DD + sc0 * 8);
    cp16(&smB[0][sr0 * STRIDE + sc0 * 8], zbB + (size_t)sr0 * DD + sc0 * 8);
    cp16(&smA[0][sr1 * STRIDE + sc1 * 8], zbA + (size_t)sr1 * DD + sc1 * 8);
    cp16(&smB[0][sr1 * STRIDE + sc1 * 8], zbB + (size_t)sr1 * DD + sc1 * 8);
    asm volatile("cp.async.commit_group;\n" ::);

#pragma unroll
    for (int kci = 0; kci < DD / KC; kci++) {
        // paced prefetch: 2 lines/thread on iters 0..3 -> full 256KB tile
        // requested by mid-GEMM, no startup burst
        if (kci < 4) {
            const int L0 = kci * 512 + tid;
            const int L1 = L0 + 256;
            prefetch_l2(dT_tile + (size_t)(L0 >> 4) * (TT * 16) + (size_t)(L0 & 15) * 128);
            prefetch_l2(dT_tile + (size_t)(L1 >> 4) * (TT * 16) + (size_t)(L1 & 15) * 128);
        }

        if (kci < DD / KC - 1) {
            const int kn = (kci + 1) * KC;
            const int nb = (kci + 1) & 1;
            cp16(&smA[nb][sr0 * STRIDE + sc0 * 8], zbA + (size_t)sr0 * DD + kn + sc0 * 8);
            cp16(&smB[nb][sr0 * STRIDE + sc0 * 8], zbB + (size_t)sr0 * DD + kn + sc0 * 8);
            cp16(&smA[nb][sr1 * STRIDE + sc1 * 8], zbA + (size_t)sr1 * DD + kn + sc1 * 8);
            cp16(&smB[nb][sr1 * STRIDE + sc1 * 8], zbB + (size_t)sr1 * DD + kn + sc1 * 8);
            asm volatile("cp.async.commit_group;\n" ::);
            asm volatile("cp.async.wait_group 1;\n" ::);
        } else {
            asm volatile("cp.async.wait_group 0;\n" ::);
        }
        __syncthreads();

        const __nv_bfloat16* A = smA[kci & 1];
        const __nv_bfloat16* B = smB[kci & 1];
#pragma unroll
        for (int k0 = 0; k0 < KC; k0 += 16) {
            uint32_t af[4][4], bf[4][2];
            const int ak = k0 + 2 * tg;
#pragma unroll
            for (int mi = 0; mi < 4; mi++) {
                const __nv_bfloat16* p = &A[(wm * 64 + mi * 16 + g) * STRIDE + ak];
                af[mi][0] = *(const uint32_t*)(p);
                af[mi][1] = *(const uint32_t*)(p + 8 * STRIDE);
                af[mi][2] = *(const uint32_t*)(p + 8);
                af[mi][3] = *(const uint32_t*)(p + 8 * STRIDE + 8);
            }
#pragma unroll
            for (int ni = 0; ni < 4; ni++) {
                const __nv_bfloat16* p = &B[(wn * 32 + ni * 8 + g) * STRIDE + ak];
                bf[ni][0] = *(const uint32_t*)(p);
                bf[ni][1] = *(const uint32_t*)(p + 8);
            }
#pragma unroll
            for (int mi = 0; mi < 4; mi++)
#pragma unroll
                for (int ni = 0; ni < 4; ni++)
                    mma_bf16(acc[mi * 4 + ni], af[mi], bf[ni]);
        }
        __syncthreads();  // all warps done reading this buffer before restage
    }

    // ---- Epilogue: stream dT tile (L2-hot), accumulate -----------------------
    float sum_w = 0.0f, sum_num = 0.0f;
#pragma unroll
    for (int mi = 0; mi < 4; mi++) {
#pragma unroll
        for (int ni = 0; ni < 4; ni++) {
#pragma unroll
            for (int j = 0; j < 4; j++) {
                int tt = wm * 64 + mi * 16 + g + ((j >> 1) ? 8 : 0);
                int ss = wn * 32 + ni * 8 + 2 * tg + (j & 1);
                float4 d4 = __ldg(&dT4[dbase + (size_t)tt * TT + ss]);
                float e = (d4.x * d4.x + d4.y * d4.y) * C_YX
                        + (d4.z * d4.z + d4.w * d4.w) * C_HW;
                float w = __expf(-e);
                float G = acc[mi * 4 + ni][j];
                sum_w   += w;
                sum_num += w * (2.0f - 2.0f * G);   // z2_t = z2_s = 1
            }
        }
    }

#pragma unroll
    for (int o = 16; o > 0; o >>= 1) {
        sum_w   += __shfl_down_sync(0xFFFFFFFFu, sum_w,   o);
        sum_num += __shfl_down_sync(0xFFFFFFFFu, sum_num, o);
    }
    if (lane == 0) { red0[warp] = sum_w; red1[warp] = sum_num; }
    __syncthreads();
    if (tid == 0) {
        float W = 0.0f, NUM = 0.0f;
#pragma unroll
        for (int i = 0; i < 8; i++) { W += red0[i]; NUM += red1[i]; }
        atomicAdd(&g_den[b], W);
        atomicAdd(&g_num[b], NUM);
    }
}

// ---------------------------------------------------------------------------
// Finalize: mean over batches of num / max(den, 1e-6)
// ---------------------------------------------------------------------------
__global__ void final_kernel(float* __restrict__ out) {
    int lane = threadIdx.x;
    float r = 0.0f;
    if (lane < BB) r = g_num[lane] / fmaxf(g_den[lane], 1e-6f);
#pragma unroll
    for (int o = 16; o > 0; o >>= 1) r += __shfl_down_sync(0xFFFFFFFFu, r, o);
    if (lane == 0) out[0] = r * (1.0f / BB);
}

extern "C" void kernel_launch(void* const* d_in, const int* in_sizes, int n_in,
                              void* d_out, int out_size) {
    const float* z  = (const float*)d_in[0];
    const float* dT = (const float*)d_in[1];
    // Defensive: z has B*T*D = 4.19M elems, gt_dT has B*T*T*4 = 67.1M.
    if (n_in >= 2 && in_sizes[0] > in_sizes[1]) {
        const float* tmp = z; z = dT; dT = tmp;
    }
    (void)out_size;

    prep_kernel<<<1024, 256>>>((const float4*)z);

    dim3 grid(TT / TILE, TT / TILE, BB);
    fused_kernel<<<grid, 256>>>((const float4*)dT);

    final_kernel<<<1, 32>>>((float*)d_out);
}